// round 13
// baseline (speedup 1.0000x reference)
#include <cuda_runtime.h>
#include <math.h>
#include <stdint.h>

#define NB      1024
#define NN      100000
#define DD      512
#define HF      672
#define TOPK    16
#define CHUNK   256
#define NCHUNK  391            // ceil(NN/256); 391*256 = 100096
#define PRE_C0  389            // prepass chunks 389,390
#define PRE_N0  (PRE_C0*CHUNK) // 99584
#define CAP     4096
#define EPSM    1e-3f          // bf16 screening margin (~14 sigma)
#define DECAYF  0.995f
#define TEMP    0.1f
#define NEGINF  (-1e30f)

#define ROWB    80             // padded smem row stride (bytes) for 32 bf16
#define STAGEB  (2 * 128 * ROWB)   // 20480 B per stage
#define NSLAB   16
#define SMEM_SCREEN (4 * STAGEB)   // 81920 B, 4-stage ring

// ---------------- device scratch ----------------
__device__ float    g_decay[NN];
__device__ float    g_scale[NCHUNK * CHUNK];
__device__ float    g_qn[(size_t)NB * DD];                         // normalized queries fp32
__device__ __align__(16) char g_qbf[(size_t)NB * DD * 2];          // Q bf16 rows
__device__ __align__(16) char g_kbf[(size_t)NCHUNK * CHUNK * DD * 2]; // K*scale bf16 rows
__device__ float    g_presims[(size_t)NB * 512];
__device__ float    g_temit[NB];                                   // t16_bf - 2*EPSM
__device__ int      g_ccnt[NB];
__device__ int      g_ci[(size_t)NB * CAP];
__device__ unsigned g_tmin_enc;

// ---------------- helpers ----------------
__device__ __forceinline__ unsigned fenc(float f) {
    unsigned u = __float_as_uint(f);
    return (u & 0x80000000u) ? ~u : (u | 0x80000000u);
}
__device__ __forceinline__ float fdec(unsigned u) {
    u = (u & 0x80000000u) ? (u ^ 0x80000000u) : ~u;
    return __uint_as_float(u);
}
__device__ __forceinline__ uint32_t packbf(float a, float b) {  // lo=a, hi=b
    uint32_t r;
    asm("cvt.rn.bf16x2.f32 %0, %1, %2;" : "=r"(r) : "f"(b), "f"(a));
    return r;
}
__device__ __forceinline__ uint32_t smem_u32(const void* p) {
    uint32_t a;
    asm("{ .reg .u64 t; cvta.to.shared.u64 t, %1; cvt.u32.u64 %0, t; }" : "=r"(a) : "l"(p));
    return a;
}
__device__ __forceinline__ void cp16s(uint32_t dst, const void* src) {
    asm volatile("cp.async.cg.shared.global [%0], [%1], 16;" :: "r"(dst), "l"(src));
}
#define CP_COMMIT() asm volatile("cp.async.commit_group;")
#define CP_WAIT(n)  asm volatile("cp.async.wait_group %0;" :: "n"(n))

__device__ __forceinline__ void ldsm_x4(uint32_t& r0, uint32_t& r1, uint32_t& r2,
                                        uint32_t& r3, uint32_t addr) {
    asm volatile("ldmatrix.sync.aligned.m8n8.x4.shared.b16 {%0,%1,%2,%3}, [%4];"
                 : "=r"(r0), "=r"(r1), "=r"(r2), "=r"(r3) : "r"(addr));
}
__device__ __forceinline__ void mma16816(float* c, const uint32_t* a, const uint32_t* b) {
    asm volatile("mma.sync.aligned.m16n8k16.row.col.f32.bf16.bf16.f32 "
        "{%0,%1,%2,%3}, {%4,%5,%6,%7}, {%8,%9}, {%0,%1,%2,%3};"
        : "+f"(c[0]), "+f"(c[1]), "+f"(c[2]), "+f"(c[3])
        : "r"(a[0]), "r"(a[1]), "r"(a[2]), "r"(a[3]), "r"(b[0]), "r"(b[1]));
}
// timestamp read: int64 LE high word of last element is 0; int32 last ~4999 != 0
__device__ __forceinline__ float decay_of(const void* ts_raw, const void* gs_raw, int n) {
    const int* w = (const int*)ts_raw;
    bool is64 = (w[NN - 1] == 0);
    long long ts = is64 ? ((const long long*)ts_raw)[n] : (long long)w[n];
    int gs = ((const int*)gs_raw)[0];
    return powf(DECAYF, (float)(gs - (int)ts));
}
// activity predicate for main-phase chunk c (identical margins everywhere)
__device__ __forceinline__ bool chunk_active(int c) {
    float t = fdec(g_tmin_enc) - 2.0f * EPSM - 1e-4f;
    float dmax = g_decay[(c + 1) * CHUNK - 1];
    return dmax * 1.001f >= t;
}

// ---------------- fused setup: init + decay + qnorm + prepass prep ----------------
// blocks [0,391): decay+init. [391,519): qnorm. [519,527): prepass chunk prep.
__global__ void k_setup(const float* __restrict__ q, const float* __restrict__ keys,
                        const void* __restrict__ ts, const void* __restrict__ gs) {
    int bx = blockIdx.x;
    int tid = threadIdx.x;
    if (bx < 391) {
        int n = bx * 256 + tid;
        if (n < NB) g_ccnt[n] = 0;
        if (n == 0) g_tmin_enc = 0xFFFFFFFFu;
        if (n < NN) g_decay[n] = decay_of(ts, gs, n);
        return;
    }
    int wid = tid >> 5, lane = tid & 31;
    if (bx < 519) {
        // qnorm: 8 rows per block
        int b = (bx - 391) * 8 + wid;
        const float* row = q + (size_t)b * DD + lane * 16;
        float v[16]; float ss = 0.f;
#pragma unroll
        for (int t = 0; t < 4; t++) {
            float4 x = *(const float4*)(row + t * 4);
            v[t*4+0] = x.x; v[t*4+1] = x.y; v[t*4+2] = x.z; v[t*4+3] = x.w;
            ss = fmaf(x.x, x.x, fmaf(x.y, x.y, fmaf(x.z, x.z, fmaf(x.w, x.w, ss))));
        }
#pragma unroll
        for (int o = 16; o; o >>= 1) ss += __shfl_xor_sync(0xffffffffu, ss, o);
        float inv = 1.0f / fmaxf(sqrtf(ss), 1e-12f);
#pragma unroll
        for (int j = 0; j < 16; j++) v[j] *= inv;
#pragma unroll
        for (int t = 0; t < 4; t++)
            *(float4*)(g_qn + (size_t)b * DD + lane * 16 + t * 4) =
                make_float4(v[t*4+0], v[t*4+1], v[t*4+2], v[t*4+3]);
        uint32_t h[8];
#pragma unroll
        for (int i = 0; i < 8; i++) h[i] = packbf(v[2*i], v[2*i+1]);
        char* dst = g_qbf + (size_t)b * 1024 + lane * 32;
        *(uint4*)dst        = make_uint4(h[0], h[1], h[2], h[3]);
        *(uint4*)(dst + 16) = make_uint4(h[4], h[5], h[6], h[7]);
        return;
    }
    // prepass chunk prep: idx in [0,8) -> (c, quarter); decay computed locally
    int idx = bx - 519;
    int c = PRE_C0 + (idx >> 2), quarter = idx & 3;
#pragma unroll
    for (int it = 0; it < 8; it++) {
        int r = quarter * 64 + wid * 8 + it;
        int n = c * CHUNK + r;
        bool ok = n < NN;
        float v[16]; float ss = 0.f;
        if (ok) {
            const float* kr = keys + (size_t)n * DD + lane * 16;
#pragma unroll
            for (int t = 0; t < 4; t++) {
                float4 x = *(const float4*)(kr + t * 4);
                v[t*4+0] = x.x; v[t*4+1] = x.y; v[t*4+2] = x.z; v[t*4+3] = x.w;
                ss = fmaf(x.x, x.x, fmaf(x.y, x.y, fmaf(x.z, x.z, fmaf(x.w, x.w, ss))));
            }
        } else {
#pragma unroll
            for (int j = 0; j < 16; j++) v[j] = 0.f;
        }
#pragma unroll
        for (int o = 16; o; o >>= 1) ss += __shfl_xor_sync(0xffffffffu, ss, o);
        float sc = ok ? decay_of(ts, gs, n) / fmaxf(sqrtf(ss), 1e-12f) : 0.f;
        if (lane == 0) g_scale[n] = sc;
        uint32_t h[8];
#pragma unroll
        for (int i = 0; i < 8; i++) h[i] = packbf(v[2*i] * sc, v[2*i+1] * sc);
        char* dst = g_kbf + (size_t)n * 1024 + lane * 32;
        *(uint4*)dst        = make_uint4(h[0], h[1], h[2], h[3]);
        *(uint4*)(dst + 16) = make_uint4(h[4], h[5], h[6], h[7]);
    }
}

// ---------------- main-phase key prep (inline activity predicate) ----------------
__global__ void k_prep_main(const float* __restrict__ keys) {
    int c = blockIdx.x;
    if (!chunk_active(c)) return;
    int wid = threadIdx.x >> 5, lane = threadIdx.x & 31;
#pragma unroll
    for (int it = 0; it < 8; it++) {
        int r = blockIdx.y * 64 + wid * 8 + it;
        int n = c * CHUNK + r;
        const float* kr = keys + (size_t)n * DD + lane * 16;
        float v[16]; float ss = 0.f;
#pragma unroll
        for (int t = 0; t < 4; t++) {
            float4 x = *(const float4*)(kr + t * 4);
            v[t*4+0] = x.x; v[t*4+1] = x.y; v[t*4+2] = x.z; v[t*4+3] = x.w;
            ss = fmaf(x.x, x.x, fmaf(x.y, x.y, fmaf(x.z, x.z, fmaf(x.w, x.w, ss))));
        }
#pragma unroll
        for (int o = 16; o; o >>= 1) ss += __shfl_xor_sync(0xffffffffu, ss, o);
        float sc = g_decay[n] / fmaxf(sqrtf(ss), 1e-12f);
        if (lane == 0) g_scale[n] = sc;
        uint32_t h[8];
#pragma unroll
        for (int i = 0; i < 8; i++) h[i] = packbf(v[2*i] * sc, v[2*i+1] * sc);
        char* dst = g_kbf + (size_t)n * 1024 + lane * 32;
        *(uint4*)dst        = make_uint4(h[0], h[1], h[2], h[3]);
        *(uint4*)(dst + 16) = make_uint4(h[4], h[5], h[6], h[7]);
    }
}

// ---------------- HMMA bf16 screening, 4-stage cp.async ring ----------------
__global__ void __launch_bounds__(256) k_screen(int pre) {
    int qt = blockIdx.x;
    int by = blockIdx.y;
    int c    = pre ? (PRE_C0 + (by >> 1)) : (by >> 1);
    int half = by & 1;
    if (!pre && !chunk_active(c)) return;
    int n0 = c * CHUNK + half * 128;

    extern __shared__ __align__(16) char smb[];
    uint32_t sb = smem_u32(smb);

    int tid = threadIdx.x;
    int wid = tid >> 5, lane = tid & 31;
    int warp_q = wid & 3, warp_n = wid >> 2;

    const char* qsrc = g_qbf + (size_t)(qt * 128) * 1024;
    const char* ksrc = g_kbf + (size_t)n0 * 1024;

    float acc[2][8][4];
#pragma unroll
    for (int mt = 0; mt < 2; mt++)
#pragma unroll
        for (int nt = 0; nt < 8; nt++)
#pragma unroll
            for (int i = 0; i < 4; i++) acc[mt][nt][i] = 0.f;

    int r0i = (tid * 2) >> 2, u0 = (tid * 2) & 3;
    int r1i = (tid * 2 + 1) >> 2, u1 = (tid * 2 + 1) & 3;

#define LOAD_SLAB(s, st) do {                                                        \
    uint32_t qb_ = sb + (st) * STAGEB;                                               \
    uint32_t kb_ = qb_ + 128 * ROWB;                                                 \
    cp16s(qb_ + r0i * ROWB + u0 * 16, qsrc + (size_t)r0i * 1024 + (s) * 64 + u0 * 16); \
    cp16s(qb_ + r1i * ROWB + u1 * 16, qsrc + (size_t)r1i * 1024 + (s) * 64 + u1 * 16); \
    cp16s(kb_ + r0i * ROWB + u0 * 16, ksrc + (size_t)r0i * 1024 + (s) * 64 + u0 * 16); \
    cp16s(kb_ + r1i * ROWB + u1 * 16, ksrc + (size_t)r1i * 1024 + (s) * 64 + u1 * 16); \
} while (0)

    LOAD_SLAB(0, 0); CP_COMMIT();
    LOAD_SLAB(1, 1); CP_COMMIT();
    LOAD_SLAB(2, 2); CP_COMMIT();

#pragma unroll
    for (int s = 0; s < NSLAB; s++) {
        if (s <= NSLAB - 3)      CP_WAIT(2);
        else if (s == NSLAB - 2) CP_WAIT(1);
        else                     CP_WAIT(0);
        __syncthreads();
        if (s + 3 < NSLAB) { LOAD_SLAB(s + 3, (s + 3) & 3); CP_COMMIT(); }

        uint32_t qb = sb + (s & 3) * STAGEB;
        uint32_t kb = qb + 128 * ROWB;
#pragma unroll
        for (int ks = 0; ks < 2; ks++) {
            uint32_t a[2][4];
#pragma unroll
            for (int mt = 0; mt < 2; mt++) {
                int row = warp_q * 32 + mt * 16 + (lane & 15);
                int unit = ks * 2 + (lane >> 4);
                ldsm_x4(a[mt][0], a[mt][1], a[mt][2], a[mt][3],
                        qb + row * ROWB + unit * 16);
            }
            uint32_t bf[8][2];
#pragma unroll
            for (int jj = 0; jj < 4; jj++) {
                int nrow = warp_n * 64 + jj * 16 + (lane & 7) + ((lane >> 4) << 3);
                int unit = ks * 2 + ((lane >> 3) & 1);
                uint32_t b0, b1, b2, b3;
                ldsm_x4(b0, b1, b2, b3, kb + nrow * ROWB + unit * 16);
                bf[2*jj][0] = b0; bf[2*jj][1] = b1;
                bf[2*jj+1][0] = b2; bf[2*jj+1][1] = b3;
            }
#pragma unroll
            for (int mt = 0; mt < 2; mt++)
#pragma unroll
                for (int nt = 0; nt < 8; nt++)
                    mma16816(acc[mt][nt], a[mt], bf[nt]);
        }
    }

    if (pre) {
        int colbase = (c - PRE_C0) * 256 + half * 128;
#pragma unroll
        for (int mt = 0; mt < 2; mt++) {
            int q = qt * 128 + warp_q * 32 + mt * 16 + (lane >> 2);
#pragma unroll
            for (int nt = 0; nt < 8; nt++) {
                int loc = warp_n * 64 + nt * 8 + (lane & 3) * 2;
                int n = n0 + loc;
                float c0 = (n     < NN) ? acc[mt][nt][0] : NEGINF;
                float c1 = (n + 1 < NN) ? acc[mt][nt][1] : NEGINF;
                float c2 = (n     < NN) ? acc[mt][nt][2] : NEGINF;
                float c3 = (n + 1 < NN) ? acc[mt][nt][3] : NEGINF;
                *(float2*)&g_presims[(size_t)q * 512 + colbase + loc] = make_float2(c0, c1);
                *(float2*)&g_presims[(size_t)(q + 8) * 512 + colbase + loc] = make_float2(c2, c3);
            }
        }
    } else {
        float tlo[2], thi[2];
#pragma unroll
        for (int mt = 0; mt < 2; mt++) {
            int q = qt * 128 + warp_q * 32 + mt * 16 + (lane >> 2);
            tlo[mt] = g_temit[q];
            thi[mt] = g_temit[q + 8];
        }
#pragma unroll
        for (int mt = 0; mt < 2; mt++) {
            int q = qt * 128 + warp_q * 32 + mt * 16 + (lane >> 2);
#pragma unroll
            for (int nt = 0; nt < 8; nt++) {
                int n = n0 + warp_n * 64 + nt * 8 + (lane & 3) * 2;
#pragma unroll
                for (int i = 0; i < 4; i++) {
                    float v = acc[mt][nt][i];
                    int qi = q + (i >> 1) * 8;
                    int ni = n + (i & 1);
                    float t = (i >> 1) ? thi[mt] : tlo[mt];
                    if (v >= t && ni < NN) {
                        int pos = atomicAdd(&g_ccnt[qi], 1);
                        if (pos < CAP) g_ci[(size_t)qi * CAP + pos] = ni;
                    }
                }
            }
        }
    }
}

// ---------------- per-query 16th-best (bf16) + prepass candidate emit ----------------
__global__ void k_t16() {
    __shared__ float sv[512];
    __shared__ float s_t16;
    int b = blockIdx.x, tid = threadIdx.x;
    sv[tid]       = g_presims[(size_t)b * 512 + tid];
    sv[tid + 256] = g_presims[(size_t)b * 512 + tid + 256];
    __syncthreads();
    float v0 = sv[tid], v1 = sv[tid + 256];
    int r0 = 0, r1 = 0;
    for (int j = 0; j < 512; j++) {
        float vj = sv[j];
        r0 += (vj > v0) || (vj == v0 && j < tid);
        r1 += (vj > v1) || (vj == v1 && j < tid + 256);
    }
    if (r0 == TOPK - 1) s_t16 = v0;
    if (r1 == TOPK - 1) s_t16 = v1;
    __syncthreads();
    float t = s_t16;
    float te = t - 2.0f * EPSM;
    if (tid == 0) {
        g_temit[b] = te;
        atomicMin(&g_tmin_enc, fenc(t));
    }
    for (int s = tid; s < 512; s += 256) {
        float v = sv[s];
        int n = PRE_N0 + s;
        if (v >= te && n < NN) {
            int pos = atomicAdd(&g_ccnt[b], 1);
            if (pos < CAP) g_ci[(size_t)b * CAP + pos] = n;
        }
    }
}

// ---------------- fused rescore + merge + softmax + gather ----------------
__global__ void k_finish(const float* __restrict__ keys,
                         const float* __restrict__ values, float* __restrict__ out) {
    extern __shared__ float s_cv[];     // CAP floats (dynamic, 16 KB)
    __shared__ float s_v[256 * 16];
    __shared__ int   s_i[256 * 16];
    __shared__ float s_rv[256];
    __shared__ int   s_ri[256];
    __shared__ float s_tv[16];
    __shared__ int   s_ti[16];
    __shared__ float s_w[16];

    int b = blockIdx.x, tid = threadIdx.x;
    int wid = tid >> 5, lane = tid & 31;
    int cnt = g_ccnt[b]; if (cnt > CAP) cnt = CAP;

    // exact fp32 rescore into smem (warp per candidate)
    float qv[16];
#pragma unroll
    for (int t = 0; t < 4; t++) {
        float4 x = *(const float4*)(g_qn + (size_t)b * DD + lane * 16 + t * 4);
        qv[t*4+0] = x.x; qv[t*4+1] = x.y; qv[t*4+2] = x.z; qv[t*4+3] = x.w;
    }
    for (int i = wid; i < cnt; i += 8) {
        int n = g_ci[(size_t)b * CAP + i];
        const float* kr = keys + (size_t)n * DD + lane * 16;
        float s = 0.f;
#pragma unroll
        for (int t = 0; t < 4; t++) {
            float4 x = *(const float4*)(kr + t * 4);
            s = fmaf(qv[t*4+0], x.x, fmaf(qv[t*4+1], x.y,
                fmaf(qv[t*4+2], x.z, fmaf(qv[t*4+3], x.w, s))));
        }
#pragma unroll
        for (int o = 16; o; o >>= 1) s += __shfl_xor_sync(0xffffffffu, s, o);
        if (lane == 0) s_cv[i] = s * g_scale[n];
    }
    __syncthreads();

    float lv[16]; int li[16];
#pragma unroll
    for (int r = 0; r < 16; r++) { lv[r] = NEGINF; li[r] = 0x7fffffff; }
    for (int i = tid; i < cnt; i += 256) {
        float v  = s_cv[i];
        int   ix = g_ci[(size_t)b * CAP + i];
        if (v > lv[15] || (v == lv[15] && ix < li[15])) {
            lv[15] = v; li[15] = ix;
            int p = 15;
            while (p > 0 && (lv[p] > lv[p - 1] || (lv[p] == lv[p - 1] && li[p] < li[p - 1]))) {
                float tv = lv[p]; lv[p] = lv[p - 1]; lv[p - 1] = tv;
                int   ti = li[p]; li[p] = li[p - 1]; li[p - 1] = ti;
                p--;
            }
        }
    }
#pragma unroll
    for (int r = 0; r < 16; r++) { s_v[tid * 16 + r] = lv[r]; s_i[tid * 16 + r] = li[r]; }
    __syncthreads();

    for (int r = 0; r < TOPK; r++) {
        float mv = NEGINF; int mi = 0x7fffffff;
#pragma unroll
        for (int k = 0; k < 16; k++) {
            float v = s_v[tid * 16 + k]; int ix = s_i[tid * 16 + k];
            if (v > mv || (v == mv && ix < mi)) { mv = v; mi = ix; }
        }
        s_rv[tid] = mv; s_ri[tid] = mi;
        __syncthreads();
        for (int s = 128; s; s >>= 1) {
            if (tid < s) {
                float v = s_rv[tid + s]; int ix = s_ri[tid + s];
                if (v > s_rv[tid] || (v == s_rv[tid] && ix < s_ri[tid])) {
                    s_rv[tid] = v; s_ri[tid] = ix;
                }
            }
            __syncthreads();
        }
        if (tid == 0) { s_tv[r] = s_rv[0]; s_ti[r] = s_ri[0]; }
        __syncthreads();
        int win = s_ti[r];
#pragma unroll
        for (int k = 0; k < 16; k++)
            if (s_i[tid * 16 + k] == win) s_v[tid * 16 + k] = NEGINF;
        __syncthreads();
    }

    if (tid == 0) {
        float m = s_tv[0];
        float e[16], S = 0.f;
        for (int k = 0; k < 16; k++) { e[k] = expf((s_tv[k] - m) / TEMP); S += e[k]; }
        float spm = 0.f;
        for (int k = 0; k < 16; k++) {
            float p = e[k] / S;
            p = (s_tv[k] >= 0.0f) ? p : 0.f;
            s_w[k] = p; spm += p;
        }
        float inv = 1.0f / (spm + 1e-8f);
        for (int k = 0; k < 16; k++) s_w[k] *= inv;
    }
    __syncthreads();

    for (int hf = tid; hf < HF; hf += 256) {
        float a = 0.f;
#pragma unroll
        for (int k = 0; k < 16; k++)
            a = fmaf(s_w[k], values[(size_t)s_ti[k] * HF + hf], a);
        out[(size_t)b * HF + hf] = a;
    }
}

// ---------------- launch ----------------
extern "C" void kernel_launch(void* const* d_in, const int* in_sizes, int n_in,
                              void* d_out, int out_size) {
    const float* query  = (const float*)d_in[0];
    const float* keys   = (const float*)d_in[1];
    const float* values = (const float*)d_in[2];
    const void*  ts     = d_in[3];
    const void*  gs     = d_in[4];
    float* out = (float*)d_out;
    (void)in_sizes; (void)n_in; (void)out_size;

    cudaFuncSetAttribute(k_screen, cudaFuncAttributeMaxDynamicSharedMemorySize, SMEM_SCREEN);
    cudaFuncSetAttribute(k_finish, cudaFuncAttributeMaxDynamicSharedMemorySize, CAP * 4);

    k_setup<<<527, 256>>>(query, keys, ts, gs);               // init+decay+qnorm+prep_pre
    k_screen<<<dim3(8, 4), 256, SMEM_SCREEN>>>(1);            // HMMA prepass -> presims
    k_t16<<<NB, 256>>>();                                     // bounds + prepass candidates
    k_prep_main<<<dim3(PRE_C0, 4), 256>>>(keys);              // active chunks prep (inline pred)
    k_screen<<<dim3(8, PRE_C0 * 2), 256, SMEM_SCREEN>>>(0);   // HMMA screen + emit
    k_finish<<<NB, 256, CAP * 4>>>(keys, values, out);        // rescore+merge+softmax+gather
}

// round 14
// speedup vs baseline: 2.6135x; 2.6135x over previous
#include <cuda_runtime.h>
#include <math.h>
#include <stdint.h>

#define NB      1024
#define NN      100000
#define DD      512
#define HF      672
#define TOPK    16
#define CHUNK   256
#define NCHUNK  391            // ceil(NN/256); 391*256 = 100096
#define PRE_C0  389            // prepass chunks 389,390
#define PRE_N0  (PRE_C0*CHUNK) // 99584
#define CAP     4096
#define EPSM    1e-3f          // bf16 screening margin (~14 sigma)
#define DECAYF  0.995f
#define TEMP    0.1f
#define NEGINF  (-1e30f)

#define ROWB    80             // padded smem row stride (bytes) for 32 bf16
#define STAGEB  (2 * 128 * ROWB)   // 20480 B per stage
#define NSLAB   16
#define SMEM_SCREEN (4 * STAGEB)   // 81920 B, 4-stage ring

// ---------------- device scratch ----------------
__device__ float    g_decay[NN];
__device__ float    g_scale[NCHUNK * CHUNK];
__device__ float    g_qn[(size_t)NB * DD];                         // normalized queries fp32
__device__ __align__(16) char g_qbf[(size_t)NB * DD * 2];          // Q bf16 rows
__device__ __align__(16) char g_kbf[(size_t)NCHUNK * CHUNK * DD * 2]; // K*scale bf16 rows
__device__ float    g_presims[(size_t)NB * 512];
__device__ float    g_temit[NB];                                   // t16_bf - 2*EPSM
__device__ int      g_ccnt[NB];
__device__ int      g_ci[(size_t)NB * CAP];
__device__ unsigned g_tmin_enc;

// ---------------- helpers ----------------
__device__ __forceinline__ unsigned fenc(float f) {
    unsigned u = __float_as_uint(f);
    return (u & 0x80000000u) ? ~u : (u | 0x80000000u);
}
__device__ __forceinline__ float fdec(unsigned u) {
    u = (u & 0x80000000u) ? (u ^ 0x80000000u) : ~u;
    return __uint_as_float(u);
}
// pack (value desc, index asc) into one monotone u64
__device__ __forceinline__ unsigned long long packvi(float v, int ix) {
    return ((unsigned long long)fenc(v) << 32) | (unsigned)(0xFFFFFFFFu - (unsigned)ix);
}
__device__ __forceinline__ float pack_v(unsigned long long p) { return fdec((unsigned)(p >> 32)); }
__device__ __forceinline__ int   pack_i(unsigned long long p) { return (int)(0xFFFFFFFFu - (unsigned)p); }

__device__ __forceinline__ uint32_t packbf(float a, float b) {  // lo=a, hi=b
    uint32_t r;
    asm("cvt.rn.bf16x2.f32 %0, %1, %2;" : "=r"(r) : "f"(b), "f"(a));
    return r;
}
__device__ __forceinline__ uint32_t smem_u32(const void* p) {
    uint32_t a;
    asm("{ .reg .u64 t; cvta.to.shared.u64 t, %1; cvt.u32.u64 %0, t; }" : "=r"(a) : "l"(p));
    return a;
}
__device__ __forceinline__ void cp16s(uint32_t dst, const void* src) {
    asm volatile("cp.async.cg.shared.global [%0], [%1], 16;" :: "r"(dst), "l"(src));
}
#define CP_COMMIT() asm volatile("cp.async.commit_group;")
#define CP_WAIT(n)  asm volatile("cp.async.wait_group %0;" :: "n"(n))

__device__ __forceinline__ void ldsm_x4(uint32_t& r0, uint32_t& r1, uint32_t& r2,
                                        uint32_t& r3, uint32_t addr) {
    asm volatile("ldmatrix.sync.aligned.m8n8.x4.shared.b16 {%0,%1,%2,%3}, [%4];"
                 : "=r"(r0), "=r"(r1), "=r"(r2), "=r"(r3) : "r"(addr));
}
__device__ __forceinline__ void mma16816(float* c, const uint32_t* a, const uint32_t* b) {
    asm volatile("mma.sync.aligned.m16n8k16.row.col.f32.bf16.bf16.f32 "
        "{%0,%1,%2,%3}, {%4,%5,%6,%7}, {%8,%9}, {%0,%1,%2,%3};"
        : "+f"(c[0]), "+f"(c[1]), "+f"(c[2]), "+f"(c[3])
        : "r"(a[0]), "r"(a[1]), "r"(a[2]), "r"(a[3]), "r"(b[0]), "r"(b[1]));
}
__device__ __forceinline__ float decay_of(const void* ts_raw, const void* gs_raw, int n) {
    const int* w = (const int*)ts_raw;
    bool is64 = (w[NN - 1] == 0);
    long long ts = is64 ? ((const long long*)ts_raw)[n] : (long long)w[n];
    int gs = ((const int*)gs_raw)[0];
    return powf(DECAYF, (float)(gs - (int)ts));
}
__device__ __forceinline__ bool chunk_active(int c) {
    float t = fdec(g_tmin_enc) - 2.0f * EPSM - 1e-4f;
    float dmax = g_decay[(c + 1) * CHUNK - 1];
    return dmax * 1.001f >= t;
}

// ---------------- fused setup: init + decay + qnorm + prepass prep ----------------
__global__ void k_setup(const float* __restrict__ q, const float* __restrict__ keys,
                        const void* __restrict__ ts, const void* __restrict__ gs) {
    int bx = blockIdx.x;
    int tid = threadIdx.x;
    if (bx < 391) {
        int n = bx * 256 + tid;
        if (n < NB) g_ccnt[n] = 0;
        if (n == 0) g_tmin_enc = 0xFFFFFFFFu;
        if (n < NN) g_decay[n] = decay_of(ts, gs, n);
        return;
    }
    int wid = tid >> 5, lane = tid & 31;
    if (bx < 519) {
        int b = (bx - 391) * 8 + wid;
        const float* row = q + (size_t)b * DD + lane * 16;
        float v[16]; float ss = 0.f;
#pragma unroll
        for (int t = 0; t < 4; t++) {
            float4 x = *(const float4*)(row + t * 4);
            v[t*4+0] = x.x; v[t*4+1] = x.y; v[t*4+2] = x.z; v[t*4+3] = x.w;
            ss = fmaf(x.x, x.x, fmaf(x.y, x.y, fmaf(x.z, x.z, fmaf(x.w, x.w, ss))));
        }
#pragma unroll
        for (int o = 16; o; o >>= 1) ss += __shfl_xor_sync(0xffffffffu, ss, o);
        float inv = 1.0f / fmaxf(sqrtf(ss), 1e-12f);
#pragma unroll
        for (int j = 0; j < 16; j++) v[j] *= inv;
#pragma unroll
        for (int t = 0; t < 4; t++)
            *(float4*)(g_qn + (size_t)b * DD + lane * 16 + t * 4) =
                make_float4(v[t*4+0], v[t*4+1], v[t*4+2], v[t*4+3]);
        uint32_t h[8];
#pragma unroll
        for (int i = 0; i < 8; i++) h[i] = packbf(v[2*i], v[2*i+1]);
        char* dst = g_qbf + (size_t)b * 1024 + lane * 32;
        *(uint4*)dst        = make_uint4(h[0], h[1], h[2], h[3]);
        *(uint4*)(dst + 16) = make_uint4(h[4], h[5], h[6], h[7]);
        return;
    }
    int idx = bx - 519;
    int c = PRE_C0 + (idx >> 2), quarter = idx & 3;
#pragma unroll
    for (int it = 0; it < 8; it++) {
        int r = quarter * 64 + wid * 8 + it;
        int n = c * CHUNK + r;
        bool ok = n < NN;
        float v[16]; float ss = 0.f;
        if (ok) {
            const float* kr = keys + (size_t)n * DD + lane * 16;
#pragma unroll
            for (int t = 0; t < 4; t++) {
                float4 x = *(const float4*)(kr + t * 4);
                v[t*4+0] = x.x; v[t*4+1] = x.y; v[t*4+2] = x.z; v[t*4+3] = x.w;
                ss = fmaf(x.x, x.x, fmaf(x.y, x.y, fmaf(x.z, x.z, fmaf(x.w, x.w, ss))));
            }
        } else {
#pragma unroll
            for (int j = 0; j < 16; j++) v[j] = 0.f;
        }
#pragma unroll
        for (int o = 16; o; o >>= 1) ss += __shfl_xor_sync(0xffffffffu, ss, o);
        float sc = ok ? decay_of(ts, gs, n) / fmaxf(sqrtf(ss), 1e-12f) : 0.f;
        if (lane == 0) g_scale[n] = sc;
        uint32_t h[8];
#pragma unroll
        for (int i = 0; i < 8; i++) h[i] = packbf(v[2*i] * sc, v[2*i+1] * sc);
        char* dst = g_kbf + (size_t)n * 1024 + lane * 32;
        *(uint4*)dst        = make_uint4(h[0], h[1], h[2], h[3]);
        *(uint4*)(dst + 16) = make_uint4(h[4], h[5], h[6], h[7]);
    }
}

// ---------------- main-phase key prep ----------------
__global__ void k_prep_main(const float* __restrict__ keys) {
    int c = blockIdx.x;
    if (!chunk_active(c)) return;
    int wid = threadIdx.x >> 5, lane = threadIdx.x & 31;
#pragma unroll
    for (int it = 0; it < 8; it++) {
        int r = blockIdx.y * 64 + wid * 8 + it;
        int n = c * CHUNK + r;
        const float* kr = keys + (size_t)n * DD + lane * 16;
        float v[16]; float ss = 0.f;
#pragma unroll
        for (int t = 0; t < 4; t++) {
            float4 x = *(const float4*)(kr + t * 4);
            v[t*4+0] = x.x; v[t*4+1] = x.y; v[t*4+2] = x.z; v[t*4+3] = x.w;
            ss = fmaf(x.x, x.x, fmaf(x.y, x.y, fmaf(x.z, x.z, fmaf(x.w, x.w, ss))));
        }
#pragma unroll
        for (int o = 16; o; o >>= 1) ss += __shfl_xor_sync(0xffffffffu, ss, o);
        float sc = g_decay[n] / fmaxf(sqrtf(ss), 1e-12f);
        if (lane == 0) g_scale[n] = sc;
        uint32_t h[8];
#pragma unroll
        for (int i = 0; i < 8; i++) h[i] = packbf(v[2*i] * sc, v[2*i+1] * sc);
        char* dst = g_kbf + (size_t)n * 1024 + lane * 32;
        *(uint4*)dst        = make_uint4(h[0], h[1], h[2], h[3]);
        *(uint4*)(dst + 16) = make_uint4(h[4], h[5], h[6], h[7]);
    }
}

// ---------------- HMMA bf16 screening, 4-stage ring, 2 CTAs/SM ----------------
__global__ void __launch_bounds__(256, 2) k_screen(int pre) {
    int qt = blockIdx.x;
    int by = blockIdx.y;
    int c    = pre ? (PRE_C0 + (by >> 1)) : (by >> 1);
    int half = by & 1;
    if (!pre && !chunk_active(c)) return;
    int n0 = c * CHUNK + half * 128;

    extern __shared__ __align__(16) char smb[];
    uint32_t sb = smem_u32(smb);

    int tid = threadIdx.x;
    int wid = tid >> 5, lane = tid & 31;
    int warp_q = wid & 3, warp_n = wid >> 2;

    const char* qsrc = g_qbf + (size_t)(qt * 128) * 1024;
    const char* ksrc = g_kbf + (size_t)n0 * 1024;

    float acc[2][8][4];
#pragma unroll
    for (int mt = 0; mt < 2; mt++)
#pragma unroll
        for (int nt = 0; nt < 8; nt++)
#pragma unroll
            for (int i = 0; i < 4; i++) acc[mt][nt][i] = 0.f;

    int r0i = (tid * 2) >> 2, u0 = (tid * 2) & 3;
    int r1i = (tid * 2 + 1) >> 2, u1 = (tid * 2 + 1) & 3;

#define LOAD_SLAB(s, st) do {                                                        \
    uint32_t qb_ = sb + (st) * STAGEB;                                               \
    uint32_t kb_ = qb_ + 128 * ROWB;                                                 \
    cp16s(qb_ + r0i * ROWB + u0 * 16, qsrc + (size_t)r0i * 1024 + (s) * 64 + u0 * 16); \
    cp16s(qb_ + r1i * ROWB + u1 * 16, qsrc + (size_t)r1i * 1024 + (s) * 64 + u1 * 16); \
    cp16s(kb_ + r0i * ROWB + u0 * 16, ksrc + (size_t)r0i * 1024 + (s) * 64 + u0 * 16); \
    cp16s(kb_ + r1i * ROWB + u1 * 16, ksrc + (size_t)r1i * 1024 + (s) * 64 + u1 * 16); \
} while (0)

    LOAD_SLAB(0, 0); CP_COMMIT();
    LOAD_SLAB(1, 1); CP_COMMIT();
    LOAD_SLAB(2, 2); CP_COMMIT();

#pragma unroll
    for (int s = 0; s < NSLAB; s++) {
        if (s <= NSLAB - 3)      CP_WAIT(2);
        else if (s == NSLAB - 2) CP_WAIT(1);
        else                     CP_WAIT(0);
        __syncthreads();
        if (s + 3 < NSLAB) { LOAD_SLAB(s + 3, (s + 3) & 3); CP_COMMIT(); }

        uint32_t qb = sb + (s & 3) * STAGEB;
        uint32_t kb = qb + 128 * ROWB;
#pragma unroll
        for (int ks = 0; ks < 2; ks++) {
            uint32_t a[2][4];
#pragma unroll
            for (int mt = 0; mt < 2; mt++) {
                int row = warp_q * 32 + mt * 16 + (lane & 15);
                int unit = ks * 2 + (lane >> 4);
                ldsm_x4(a[mt][0], a[mt][1], a[mt][2], a[mt][3],
                        qb + row * ROWB + unit * 16);
            }
            uint32_t bf[8][2];
#pragma unroll
            for (int jj = 0; jj < 4; jj++) {
                int nrow = warp_n * 64 + jj * 16 + (lane & 7) + ((lane >> 4) << 3);
                int unit = ks * 2 + ((lane >> 3) & 1);
                uint32_t b0, b1, b2, b3;
                ldsm_x4(b0, b1, b2, b3, kb + nrow * ROWB + unit * 16);
                bf[2*jj][0] = b0; bf[2*jj][1] = b1;
                bf[2*jj+1][0] = b2; bf[2*jj+1][1] = b3;
            }
#pragma unroll
            for (int mt = 0; mt < 2; mt++)
#pragma unroll
                for (int nt = 0; nt < 8; nt++)
                    mma16816(acc[mt][nt], a[mt], bf[nt]);
        }
    }

    if (pre) {
        int colbase = (c - PRE_C0) * 256 + half * 128;
#pragma unroll
        for (int mt = 0; mt < 2; mt++) {
            int q = qt * 128 + warp_q * 32 + mt * 16 + (lane >> 2);
#pragma unroll
            for (int nt = 0; nt < 8; nt++) {
                int loc = warp_n * 64 + nt * 8 + (lane & 3) * 2;
                int n = n0 + loc;
                float c0 = (n     < NN) ? acc[mt][nt][0] : NEGINF;
                float c1 = (n + 1 < NN) ? acc[mt][nt][1] : NEGINF;
                float c2 = (n     < NN) ? acc[mt][nt][2] : NEGINF;
                float c3 = (n + 1 < NN) ? acc[mt][nt][3] : NEGINF;
                *(float2*)&g_presims[(size_t)q * 512 + colbase + loc] = make_float2(c0, c1);
                *(float2*)&g_presims[(size_t)(q + 8) * 512 + colbase + loc] = make_float2(c2, c3);
            }
        }
    } else {
        float tlo[2], thi[2];
#pragma unroll
        for (int mt = 0; mt < 2; mt++) {
            int q = qt * 128 + warp_q * 32 + mt * 16 + (lane >> 2);
            tlo[mt] = g_temit[q];
            thi[mt] = g_temit[q + 8];
        }
#pragma unroll
        for (int mt = 0; mt < 2; mt++) {
            int q = qt * 128 + warp_q * 32 + mt * 16 + (lane >> 2);
#pragma unroll
            for (int nt = 0; nt < 8; nt++) {
                int n = n0 + warp_n * 64 + nt * 8 + (lane & 3) * 2;
#pragma unroll
                for (int i = 0; i < 4; i++) {
                    float v = acc[mt][nt][i];
                    int qi = q + (i >> 1) * 8;
                    int ni = n + (i & 1);
                    float t = (i >> 1) ? thi[mt] : tlo[mt];
                    if (v >= t && ni < NN) {
                        int pos = atomicAdd(&g_ccnt[qi], 1);
                        if (pos < CAP) g_ci[(size_t)qi * CAP + pos] = ni;
                    }
                }
            }
        }
    }
}

// ---------------- per-query 16th-best via 16x packed max-extraction ----------------
__global__ void k_t16() {
    __shared__ float sv[512];
    __shared__ unsigned long long s_best;
    int b = blockIdx.x, tid = threadIdx.x;
    int lane = tid & 31;
    sv[tid]       = g_presims[(size_t)b * 512 + tid];
    sv[tid + 256] = g_presims[(size_t)b * 512 + tid + 256];
    float t = NEGINF;
    for (int r = 0; r < TOPK; r++) {
        if (tid == 0) s_best = 0ULL;
        __syncthreads();
        unsigned long long m = packvi(sv[tid], tid);
        unsigned long long m2 = packvi(sv[tid + 256], tid + 256);
        if (m2 > m) m = m2;
#pragma unroll
        for (int o = 16; o; o >>= 1) {
            unsigned long long om = __shfl_xor_sync(0xffffffffu, m, o);
            if (om > m) m = om;
        }
        if (lane == 0) atomicMax(&s_best, m);
        __syncthreads();
        unsigned long long w = s_best;
        int wi = pack_i(w);
        if (wi == tid) sv[tid] = NEGINF;
        if (wi == tid + 256) sv[tid + 256] = NEGINF;
        if (r == TOPK - 1) t = pack_v(w);
        __syncthreads();
    }
    float te = t - 2.0f * EPSM;
    if (tid == 0) {
        g_temit[b] = te;
        atomicMin(&g_tmin_enc, fenc(t));
    }
    // emit from global (sv was destroyed by extraction)
    for (int s = tid; s < 512; s += 256) {
        float v = g_presims[(size_t)b * 512 + s];
        int n = PRE_N0 + s;
        if (v >= te && n < NN) {
            int pos = atomicAdd(&g_ccnt[b], 1);
            if (pos < CAP) g_ci[(size_t)b * CAP + pos] = n;
        }
    }
}

// ---------------- fused rescore + select + softmax + gather ----------------
__global__ void k_finish(const float* __restrict__ keys,
                         const float* __restrict__ values, float* __restrict__ out) {
    extern __shared__ float s_dyn[];                 // [CAP] values + [CAP] indices
    float* s_cv = s_dyn;
    int*   s_ci = (int*)(s_dyn + CAP);
    __shared__ unsigned long long s_best;
    __shared__ float s_tv[16];
    __shared__ int   s_ti[16];
    __shared__ float s_w[16];

    int b = blockIdx.x, tid = threadIdx.x;
    int wid = tid >> 5, lane = tid & 31;
    int cnt = g_ccnt[b]; if (cnt > CAP) cnt = CAP;

    // exact fp32 rescore into smem (warp per candidate)
    float qv[16];
#pragma unroll
    for (int t = 0; t < 4; t++) {
        float4 x = *(const float4*)(g_qn + (size_t)b * DD + lane * 16 + t * 4);
        qv[t*4+0] = x.x; qv[t*4+1] = x.y; qv[t*4+2] = x.z; qv[t*4+3] = x.w;
    }
    for (int i = wid; i < cnt; i += 8) {
        int n = g_ci[(size_t)b * CAP + i];
        const float* kr = keys + (size_t)n * DD + lane * 16;
        float s = 0.f;
#pragma unroll
        for (int t = 0; t < 4; t++) {
            float4 x = *(const float4*)(kr + t * 4);
            s = fmaf(qv[t*4+0], x.x, fmaf(qv[t*4+1], x.y,
                fmaf(qv[t*4+2], x.z, fmaf(qv[t*4+3], x.w, s))));
        }
#pragma unroll
        for (int o = 16; o; o >>= 1) s += __shfl_xor_sync(0xffffffffu, s, o);
        if (lane == 0) { s_cv[i] = s * g_scale[n]; s_ci[i] = n; }
    }
    __syncthreads();

    // 16 rounds of packed max-extraction (value desc, index asc)
    for (int r = 0; r < TOPK; r++) {
        if (tid == 0) s_best = 0ULL;
        __syncthreads();
        unsigned long long m = 0ULL;
        for (int i = tid; i < cnt; i += 256) {
            unsigned long long p = packvi(s_cv[i], s_ci[i]);
            if (p > m) m = p;
        }
#pragma unroll
        for (int o = 16; o; o >>= 1) {
            unsigned long long om = __shfl_xor_sync(0xffffffffu, m, o);
            if (om > m) m = om;
        }
        if (lane == 0 && m) atomicMax(&s_best, m);
        __syncthreads();
        unsigned long long w = s_best;
        int wi = pack_i(w);
        if (tid == 0) { s_tv[r] = pack_v(w); s_ti[r] = wi; }
        for (int i = tid; i < cnt; i += 256)
            if (s_ci[i] == wi) s_cv[i] = NEGINF;
        __syncthreads();
    }

    if (tid == 0) {
        float m = s_tv[0];
        float e[16], S = 0.f;
        for (int k = 0; k < 16; k++) { e[k] = expf((s_tv[k] - m) / TEMP); S += e[k]; }
        float spm = 0.f;
        for (int k = 0; k < 16; k++) {
            float p = e[k] / S;
            p = (s_tv[k] >= 0.0f) ? p : 0.f;
            s_w[k] = p; spm += p;
        }
        float inv = 1.0f / (spm + 1e-8f);
        for (int k = 0; k < 16; k++) s_w[k] *= inv;
    }
    __syncthreads();

    for (int hf = tid; hf < HF; hf += 256) {
        float a = 0.f;
#pragma unroll
        for (int k = 0; k < 16; k++)
            a = fmaf(s_w[k], values[(size_t)s_ti[k] * HF + hf], a);
        out[(size_t)b * HF + hf] = a;
    }
}

// ---------------- launch ----------------
extern "C" void kernel_launch(void* const* d_in, const int* in_sizes, int n_in,
                              void* d_out, int out_size) {
    const float* query  = (const float*)d_in[0];
    const float* keys   = (const float*)d_in[1];
    const float* values = (const float*)d_in[2];
    const void*  ts     = d_in[3];
    const void*  gs     = d_in[4];
    float* out = (float*)d_out;
    (void)in_sizes; (void)n_in; (void)out_size;

    cudaFuncSetAttribute(k_screen, cudaFuncAttributeMaxDynamicSharedMemorySize, SMEM_SCREEN);
    cudaFuncSetAttribute(k_finish, cudaFuncAttributeMaxDynamicSharedMemorySize, CAP * 8);

    k_setup<<<527, 256>>>(query, keys, ts, gs);               // init+decay+qnorm+prep_pre
    k_screen<<<dim3(8, 4), 256, SMEM_SCREEN>>>(1);            // HMMA prepass -> presims
    k_t16<<<NB, 256>>>();                                     // bounds + prepass candidates
    k_prep_main<<<dim3(PRE_C0, 4), 256>>>(keys);              // active chunks prep
    k_screen<<<dim3(8, PRE_C0 * 2), 256, SMEM_SCREEN>>>(0);   // HMMA screen + emit
    k_finish<<<NB, 256, CAP * 8>>>(keys, values, out);        // rescore+select+softmax+gather
}

// round 15
// speedup vs baseline: 2.6247x; 1.0043x over previous
#include <cuda_runtime.h>
#include <math.h>
#include <stdint.h>

#define NB      1024
#define NN      100000
#define DD      512
#define HF      672
#define TOPK    16
#define CHUNK   256
#define NCHUNK  391            // ceil(NN/256); 391*256 = 100096
#define PRE_C0  389            // prepass chunks 389,390
#define PRE_N0  (PRE_C0*CHUNK) // 99584
#define PREP_U0 316            // chunks >= this prepped unconditionally in setup
#define CAP     4096
#define EPSM    1e-3f          // bf16 screening margin (~14 sigma)
#define DECAYF  0.995f
#define TEMP    0.1f
#define NEGINF  (-1e30f)

#define ROWB    80             // padded smem row stride (bytes) for 32 bf16
#define STAGEB  (2 * 128 * ROWB)   // 20480 B per stage
#define SMEM_SCREEN (4 * STAGEB)   // 81920 B, 4-stage ring

// setup block partition
#define SB_QN   391
#define SB_PP   (SB_QN + 128)              // 519
#define SB_PU   (SB_PP + 8)                // 527
#define SB_END  (SB_PU + (PRE_C0 - PREP_U0) * 4)   // 527 + 292 = 819

// ---------------- device scratch ----------------
__device__ float    g_decay[NN];
__device__ float    g_scale[NCHUNK * CHUNK];
__device__ float    g_qn[(size_t)NB * DD];
__device__ __align__(16) char g_qbf[(size_t)NB * DD * 2];
__device__ __align__(16) char g_kbf[(size_t)NCHUNK * CHUNK * DD * 2];
__device__ float    g_presims[(size_t)2 * NB * 512];   // two K-half partial planes
__device__ float    g_temit[NB];
__device__ int      g_ccnt[NB];
__device__ int      g_ci[(size_t)NB * CAP];
__device__ unsigned g_tmin_enc;
__device__ unsigned g_tqt_enc[8];
__device__ int      g_wl[8 * PRE_C0];
__device__ int      g_wlcnt[8];

// ---------------- helpers ----------------
__device__ __forceinline__ unsigned fenc(float f) {
    unsigned u = __float_as_uint(f);
    return (u & 0x80000000u) ? ~u : (u | 0x80000000u);
}
__device__ __forceinline__ float fdec(unsigned u) {
    u = (u & 0x80000000u) ? (u ^ 0x80000000u) : ~u;
    return __uint_as_float(u);
}
__device__ __forceinline__ unsigned long long packvi(float v, int ix) {
    return ((unsigned long long)fenc(v) << 32) | (unsigned)(0xFFFFFFFFu - (unsigned)ix);
}
__device__ __forceinline__ float pack_v(unsigned long long p) { return fdec((unsigned)(p >> 32)); }
__device__ __forceinline__ int   pack_i(unsigned long long p) { return (int)(0xFFFFFFFFu - (unsigned)p); }

__device__ __forceinline__ uint32_t packbf(float a, float b) {
    uint32_t r;
    asm("cvt.rn.bf16x2.f32 %0, %1, %2;" : "=r"(r) : "f"(b), "f"(a));
    return r;
}
__device__ __forceinline__ uint32_t smem_u32(const void* p) {
    uint32_t a;
    asm("{ .reg .u64 t; cvta.to.shared.u64 t, %1; cvt.u32.u64 %0, t; }" : "=r"(a) : "l"(p));
    return a;
}
__device__ __forceinline__ void cp16s(uint32_t dst, const void* src) {
    asm volatile("cp.async.cg.shared.global [%0], [%1], 16;" :: "r"(dst), "l"(src));
}
#define CP_COMMIT() asm volatile("cp.async.commit_group;")
#define CP_WAIT(n)  asm volatile("cp.async.wait_group %0;" :: "n"(n))

__device__ __forceinline__ void ldsm_x4(uint32_t& r0, uint32_t& r1, uint32_t& r2,
                                        uint32_t& r3, uint32_t addr) {
    asm volatile("ldmatrix.sync.aligned.m8n8.x4.shared.b16 {%0,%1,%2,%3}, [%4];"
                 : "=r"(r0), "=r"(r1), "=r"(r2), "=r"(r3) : "r"(addr));
}
__device__ __forceinline__ void mma16816(float* c, const uint32_t* a, const uint32_t* b) {
    asm volatile("mma.sync.aligned.m16n8k16.row.col.f32.bf16.bf16.f32 "
        "{%0,%1,%2,%3}, {%4,%5,%6,%7}, {%8,%9}, {%0,%1,%2,%3};"
        : "+f"(c[0]), "+f"(c[1]), "+f"(c[2]), "+f"(c[3])
        : "r"(a[0]), "r"(a[1]), "r"(a[2]), "r"(a[3]), "r"(b[0]), "r"(b[1]));
}
__device__ __forceinline__ float decay_of(const void* ts_raw, const void* gs_raw, int n) {
    const int* w = (const int*)ts_raw;
    bool is64 = (w[NN - 1] == 0);
    long long ts = is64 ? ((const long long*)ts_raw)[n] : (long long)w[n];
    int gs = ((const int*)gs_raw)[0];
    return powf(DECAYF, (float)(gs - (int)ts));
}
__device__ __forceinline__ bool chunk_active(int c) {
    float t = fdec(g_tmin_enc) - 2.0f * EPSM - 1e-4f;
    float dmax = g_decay[(c + 1) * CHUNK - 1];
    return dmax * 1.001f >= t;
}

// shared prep body: one (chunk, quarter) -> 64 rows of bf16*scale + g_scale
__device__ __forceinline__ void prep_quarter(const float* __restrict__ keys, int c, int quarter,
                                             bool local_decay, const void* ts, const void* gs) {
    int wid = threadIdx.x >> 5, lane = threadIdx.x & 31;
#pragma unroll
    for (int it = 0; it < 8; it++) {
        int r = quarter * 64 + wid * 8 + it;
        int n = c * CHUNK + r;
        bool ok = n < NN;
        float v[16]; float ss = 0.f;
        if (ok) {
            const float* kr = keys + (size_t)n * DD + lane * 16;
#pragma unroll
            for (int t = 0; t < 4; t++) {
                float4 x = *(const float4*)(kr + t * 4);
                v[t*4+0] = x.x; v[t*4+1] = x.y; v[t*4+2] = x.z; v[t*4+3] = x.w;
                ss = fmaf(x.x, x.x, fmaf(x.y, x.y, fmaf(x.z, x.z, fmaf(x.w, x.w, ss))));
            }
        } else {
#pragma unroll
            for (int j = 0; j < 16; j++) v[j] = 0.f;
        }
#pragma unroll
        for (int o = 16; o; o >>= 1) ss += __shfl_xor_sync(0xffffffffu, ss, o);
        float dk = ok ? (local_decay ? decay_of(ts, gs, n) : g_decay[n]) : 0.f;
        float sc = ok ? dk / fmaxf(sqrtf(ss), 1e-12f) : 0.f;
        if (lane == 0) g_scale[n] = sc;
        uint32_t h[8];
#pragma unroll
        for (int i = 0; i < 8; i++) h[i] = packbf(v[2*i] * sc, v[2*i+1] * sc);
        char* dst = g_kbf + (size_t)n * 1024 + lane * 32;
        *(uint4*)dst        = make_uint4(h[0], h[1], h[2], h[3]);
        *(uint4*)(dst + 16) = make_uint4(h[4], h[5], h[6], h[7]);
    }
}

// ---------------- fused setup ----------------
// [0,391): decay+init. [391,519): qnorm. [519,527): prepass prep. [527,819): prep [316,389).
__global__ void k_setup(const float* __restrict__ q, const float* __restrict__ keys,
                        const void* __restrict__ ts, const void* __restrict__ gs) {
    int bx = blockIdx.x;
    int tid = threadIdx.x;
    if (bx < SB_QN) {
        int n = bx * 256 + tid;
        if (n < NB) g_ccnt[n] = 0;
        if (bx == 0 && tid < 8) g_tqt_enc[tid] = 0xFFFFFFFFu;
        if (n == 0) g_tmin_enc = 0xFFFFFFFFu;
        if (n < NN) g_decay[n] = decay_of(ts, gs, n);
        return;
    }
    int wid = tid >> 5, lane = tid & 31;
    if (bx < SB_PP) {
        int b = (bx - SB_QN) * 8 + wid;
        const float* row = q + (size_t)b * DD + lane * 16;
        float v[16]; float ss = 0.f;
#pragma unroll
        for (int t = 0; t < 4; t++) {
            float4 x = *(const float4*)(row + t * 4);
            v[t*4+0] = x.x; v[t*4+1] = x.y; v[t*4+2] = x.z; v[t*4+3] = x.w;
            ss = fmaf(x.x, x.x, fmaf(x.y, x.y, fmaf(x.z, x.z, fmaf(x.w, x.w, ss))));
        }
#pragma unroll
        for (int o = 16; o; o >>= 1) ss += __shfl_xor_sync(0xffffffffu, ss, o);
        float inv = 1.0f / fmaxf(sqrtf(ss), 1e-12f);
#pragma unroll
        for (int j = 0; j < 16; j++) v[j] *= inv;
#pragma unroll
        for (int t = 0; t < 4; t++)
            *(float4*)(g_qn + (size_t)b * DD + lane * 16 + t * 4) =
                make_float4(v[t*4+0], v[t*4+1], v[t*4+2], v[t*4+3]);
        uint32_t h[8];
#pragma unroll
        for (int i = 0; i < 8; i++) h[i] = packbf(v[2*i], v[2*i+1]);
        char* dst = g_qbf + (size_t)b * 1024 + lane * 32;
        *(uint4*)dst        = make_uint4(h[0], h[1], h[2], h[3]);
        *(uint4*)(dst + 16) = make_uint4(h[4], h[5], h[6], h[7]);
        return;
    }
    if (bx < SB_PU) {
        int idx = bx - SB_PP;
        prep_quarter(keys, PRE_C0 + (idx >> 2), idx & 3, true, ts, gs);
        return;
    }
    int idx = bx - SB_PU;
    prep_quarter(keys, PREP_U0 + (idx >> 2), idx & 3, true, ts, gs);
}

// ---------------- HMMA screen body (shared by pre/main) ----------------
__device__ __forceinline__ void screen_tile(uint32_t sb, const char* qsrc, const char* ksrc,
                                            int slab0, int nslab, float acc[2][8][4]) {
    int tid = threadIdx.x;
    int wid = tid >> 5, lane = tid & 31;
    int warp_q = wid & 3, warp_n = wid >> 2;
    int r0i = (tid * 2) >> 2, u0 = (tid * 2) & 3;
    int r1i = (tid * 2 + 1) >> 2, u1 = (tid * 2 + 1) & 3;

#define LOAD_SLAB(s, st) do {                                                        \
    uint32_t qb_ = sb + (st) * STAGEB;                                               \
    uint32_t kb_ = qb_ + 128 * ROWB;                                                 \
    int as_ = slab0 + (s);                                                           \
    cp16s(qb_ + r0i * ROWB + u0 * 16, qsrc + (size_t)r0i * 1024 + as_ * 64 + u0 * 16); \
    cp16s(qb_ + r1i * ROWB + u1 * 16, qsrc + (size_t)r1i * 1024 + as_ * 64 + u1 * 16); \
    cp16s(kb_ + r0i * ROWB + u0 * 16, ksrc + (size_t)r0i * 1024 + as_ * 64 + u0 * 16); \
    cp16s(kb_ + r1i * ROWB + u1 * 16, ksrc + (size_t)r1i * 1024 + as_ * 64 + u1 * 16); \
} while (0)

    LOAD_SLAB(0, 0); CP_COMMIT();
    LOAD_SLAB(1, 1); CP_COMMIT();
    LOAD_SLAB(2, 2); CP_COMMIT();

    for (int s = 0; s < nslab; s++) {
        if (s <= nslab - 3)      CP_WAIT(2);
        else if (s == nslab - 2) CP_WAIT(1);
        else                     CP_WAIT(0);
        __syncthreads();
        if (s + 3 < nslab) { LOAD_SLAB(s + 3, (s + 3) & 3); CP_COMMIT(); }

        uint32_t qb = sb + (s & 3) * STAGEB;
        uint32_t kb = qb + 128 * ROWB;
#pragma unroll
        for (int ks = 0; ks < 2; ks++) {
            uint32_t a[2][4];
#pragma unroll
            for (int mt = 0; mt < 2; mt++) {
                int row = warp_q * 32 + mt * 16 + (lane & 15);
                int unit = ks * 2 + (lane >> 4);
                ldsm_x4(a[mt][0], a[mt][1], a[mt][2], a[mt][3],
                        qb + row * ROWB + unit * 16);
            }
            uint32_t bf[8][2];
#pragma unroll
            for (int jj = 0; jj < 4; jj++) {
                int nrow = warp_n * 64 + jj * 16 + (lane & 7) + ((lane >> 4) << 3);
                int unit = ks * 2 + ((lane >> 3) & 1);
                uint32_t b0, b1, b2, b3;
                ldsm_x4(b0, b1, b2, b3, kb + nrow * ROWB + unit * 16);
                bf[2*jj][0] = b0; bf[2*jj][1] = b1;
                bf[2*jj+1][0] = b2; bf[2*jj+1][1] = b3;
            }
#pragma unroll
            for (int mt = 0; mt < 2; mt++)
#pragma unroll
                for (int nt = 0; nt < 8; nt++)
                    mma16816(acc[mt][nt], a[mt], bf[nt]);
        }
    }
#undef LOAD_SLAB
}

// ---------------- prepass screen: grid (8, 8) = (qt, nq 0..3 x khalf 0..1) ----------------
__global__ void __launch_bounds__(256, 2) k_screen_pre() {
    int qt = blockIdx.x;
    int nq = blockIdx.y & 3, kh = blockIdx.y >> 2;
    int c = PRE_C0 + (nq >> 1), half = nq & 1;
    int n0 = c * CHUNK + half * 128;

    extern __shared__ __align__(16) char smb[];
    uint32_t sb = smem_u32(smb);
    int tid = threadIdx.x;
    int wid = tid >> 5, lane = tid & 31;
    int warp_q = wid & 3, warp_n = wid >> 2;

    float acc[2][8][4];
#pragma unroll
    for (int mt = 0; mt < 2; mt++)
#pragma unroll
        for (int nt = 0; nt < 8; nt++)
#pragma unroll
            for (int i = 0; i < 4; i++) acc[mt][nt][i] = 0.f;

    screen_tile(sb, g_qbf + (size_t)(qt * 128) * 1024, g_kbf + (size_t)n0 * 1024,
                kh * 8, 8, acc);

    float* plane = g_presims + (size_t)kh * NB * 512;
    int colbase = nq * 128;
#pragma unroll
    for (int mt = 0; mt < 2; mt++) {
        int q = qt * 128 + warp_q * 32 + mt * 16 + (lane >> 2);
#pragma unroll
        for (int nt = 0; nt < 8; nt++) {
            int loc = warp_n * 64 + nt * 8 + (lane & 3) * 2;
            *(float2*)&plane[(size_t)q * 512 + colbase + loc] =
                make_float2(acc[mt][nt][0], acc[mt][nt][1]);
            *(float2*)&plane[(size_t)(q + 8) * 512 + colbase + loc] =
                make_float2(acc[mt][nt][2], acc[mt][nt][3]);
        }
    }
}

// ---------------- t16: sum K-halves, 16x packed max-extraction, thresholds + emit ----------------
__global__ void k_t16() {
    __shared__ float sv[512];
    __shared__ float svO[512];
    __shared__ unsigned long long s_best;
    int b = blockIdx.x, tid = threadIdx.x;
    int lane = tid & 31;
    const float* P0 = g_presims + (size_t)b * 512;
    const float* P1 = g_presims + (size_t)(NB + b) * 512;
#pragma unroll
    for (int s = tid; s < 512; s += 256) {
        float v = (PRE_N0 + s < NN) ? P0[s] + P1[s] : NEGINF;
        sv[s] = v; svO[s] = v;
    }
    float t = NEGINF;
    for (int r = 0; r < TOPK; r++) {
        if (tid == 0) s_best = 0ULL;
        __syncthreads();
        unsigned long long m = packvi(sv[tid], tid);
        unsigned long long m2 = packvi(sv[tid + 256], tid + 256);
        if (m2 > m) m = m2;
#pragma unroll
        for (int o = 16; o; o >>= 1) {
            unsigned long long om = __shfl_xor_sync(0xffffffffu, m, o);
            if (om > m) m = om;
        }
        if (lane == 0) atomicMax(&s_best, m);
        __syncthreads();
        unsigned long long w = s_best;
        int wi = pack_i(w);
        if (wi == tid) sv[tid] = NEGINF;
        if (wi == tid + 256) sv[tid + 256] = NEGINF;
        if (r == TOPK - 1) t = pack_v(w);
        __syncthreads();
    }
    float te = t - 2.0f * EPSM;
    if (tid == 0) {
        g_temit[b] = te;
        atomicMin(&g_tmin_enc, fenc(t));
        atomicMin(&g_tqt_enc[b >> 7], fenc(t));
    }
    for (int s = tid; s < 512; s += 256) {
        float v = svO[s];
        int n = PRE_N0 + s;
        if (v >= te && n < NN) {
            int pos = atomicAdd(&g_ccnt[b], 1);
            if (pos < CAP) g_ci[(size_t)b * CAP + pos] = n;
        }
    }
}

// ---------------- mid: block 0 builds per-qt worklists; rest = fix-up prep c<316 ----------------
__global__ void k_mid(const float* __restrict__ keys) {
    if (blockIdx.x == 0) {
        int wid = threadIdx.x >> 5, lane = threadIdx.x & 31;
        if (wid < 8) {
            float t = fdec(g_tqt_enc[wid]) - 2.0f * EPSM - 1e-4f;
            int cnt = 0;
            for (int base = 0; base < PRE_C0; base += 32) {
                int c = base + lane;
                bool act = false;
                if (c < PRE_C0) {
                    float dmax = g_decay[(c + 1) * CHUNK - 1];
                    act = dmax * 1.001f >= t;
                }
                unsigned mask = __ballot_sync(0xffffffffu, act);
                if (act) {
                    int pos = cnt + __popc(mask & ((1u << lane) - 1));
                    g_wl[wid * PRE_C0 + pos] = c;
                }
                cnt += __popc(mask);
            }
            if (lane == 0) g_wlcnt[wid] = cnt;
        }
        return;
    }
    int idx = blockIdx.x - 1;
    int c = idx >> 2;
    if (!chunk_active(c)) return;     // global predicate (union of per-qt)
    prep_quarter(keys, c, idx & 3, false, 0, 0);
}

// ---------------- main screen: worklist-driven ----------------
__global__ void __launch_bounds__(256, 2) k_screen_main() {
    int qt = blockIdx.x;
    int i = blockIdx.y >> 1, half = blockIdx.y & 1;
    if (i >= g_wlcnt[qt]) return;
    int c = g_wl[qt * PRE_C0 + i];
    int n0 = c * CHUNK + half * 128;

    extern __shared__ __align__(16) char smb[];
    uint32_t sb = smem_u32(smb);
    int tid = threadIdx.x;
    int wid = tid >> 5, lane = tid & 31;
    int warp_q = wid & 3, warp_n = wid >> 2;

    float acc[2][8][4];
#pragma unroll
    for (int mt = 0; mt < 2; mt++)
#pragma unroll
        for (int nt = 0; nt < 8; nt++)
#pragma unroll
            for (int j = 0; j < 4; j++) acc[mt][nt][j] = 0.f;

    screen_tile(sb, g_qbf + (size_t)(qt * 128) * 1024, g_kbf + (size_t)n0 * 1024,
                0, 16, acc);

    float tlo[2], thi[2];
#pragma unroll
    for (int mt = 0; mt < 2; mt++) {
        int q = qt * 128 + warp_q * 32 + mt * 16 + (lane >> 2);
        tlo[mt] = g_temit[q];
        thi[mt] = g_temit[q + 8];
    }
#pragma unroll
    for (int mt = 0; mt < 2; mt++) {
        int q = qt * 128 + warp_q * 32 + mt * 16 + (lane >> 2);
#pragma unroll
        for (int nt = 0; nt < 8; nt++) {
            int n = n0 + warp_n * 64 + nt * 8 + (lane & 3) * 2;
#pragma unroll
            for (int j = 0; j < 4; j++) {
                float v = acc[mt][nt][j];
                int qi = q + (j >> 1) * 8;
                int ni = n + (j & 1);
                float t = (j >> 1) ? thi[mt] : tlo[mt];
                if (v >= t && ni < NN) {
                    int pos = atomicAdd(&g_ccnt[qi], 1);
                    if (pos < CAP) g_ci[(size_t)qi * CAP + pos] = ni;
                }
            }
        }
    }
}

// ---------------- fused rescore + select + softmax + gather ----------------
__global__ void k_finish(const float* __restrict__ keys,
                         const float* __restrict__ values, float* __restrict__ out) {
    extern __shared__ float s_dyn[];
    float* s_cv = s_dyn;
    int*   s_ci = (int*)(s_dyn + CAP);
    __shared__ unsigned long long s_best;
    __shared__ float s_tv[16];
    __shared__ int   s_ti[16];
    __shared__ float s_w[16];

    int b = blockIdx.x, tid = threadIdx.x;
    int wid = tid >> 5, lane = tid & 31;
    int cnt = g_ccnt[b]; if (cnt > CAP) cnt = CAP;

    float qv[16];
#pragma unroll
    for (int t = 0; t < 4; t++) {
        float4 x = *(const float4*)(g_qn + (size_t)b * DD + lane * 16 + t * 4);
        qv[t*4+0] = x.x; qv[t*4+1] = x.y; qv[t*4+2] = x.z; qv[t*4+3] = x.w;
    }
    for (int i = wid; i < cnt; i += 8) {
        int n = g_ci[(size_t)b * CAP + i];
        const float* kr = keys + (size_t)n * DD + lane * 16;
        float s = 0.f;
#pragma unroll
        for (int t = 0; t < 4; t++) {
            float4 x = *(const float4*)(kr + t * 4);
            s = fmaf(qv[t*4+0], x.x, fmaf(qv[t*4+1], x.y,
                fmaf(qv[t*4+2], x.z, fmaf(qv[t*4+3], x.w, s))));
        }
#pragma unroll
        for (int o = 16; o; o >>= 1) s += __shfl_xor_sync(0xffffffffu, s, o);
        if (lane == 0) { s_cv[i] = s * g_scale[n]; s_ci[i] = n; }
    }
    __syncthreads();

    for (int r = 0; r < TOPK; r++) {
        if (tid == 0) s_best = 0ULL;
        __syncthreads();
        unsigned long long m = 0ULL;
        for (int i = tid; i < cnt; i += 256) {
            unsigned long long p = packvi(s_cv[i], s_ci[i]);
            if (p > m) m = p;
        }
#pragma unroll
        for (int o = 16; o; o >>= 1) {
            unsigned long long om = __shfl_xor_sync(0xffffffffu, m, o);
            if (om > m) m = om;
        }
        if (lane == 0 && m) atomicMax(&s_best, m);
        __syncthreads();
        unsigned long long w = s_best;
        int wi = pack_i(w);
        if (tid == 0) { s_tv[r] = pack_v(w); s_ti[r] = wi; }
        for (int i = tid; i < cnt; i += 256)
            if (s_ci[i] == wi) s_cv[i] = NEGINF;
        __syncthreads();
    }

    if (tid == 0) {
        float m = s_tv[0];
        float e[16], S = 0.f;
        for (int k = 0; k < 16; k++) { e[k] = expf((s_tv[k] - m) / TEMP); S += e[k]; }
        float spm = 0.f;
        for (int k = 0; k < 16; k++) {
            float p = e[k] / S;
            p = (s_tv[k] >= 0.0f) ? p : 0.f;
            s_w[k] = p; spm += p;
        }
        float inv = 1.0f / (spm + 1e-8f);
        for (int k = 0; k < 16; k++) s_w[k] *= inv;
    }
    __syncthreads();

    for (int hf = tid; hf < HF; hf += 256) {
        float a = 0.f;
#pragma unroll
        for (int k = 0; k < 16; k++)
            a = fmaf(s_w[k], values[(size_t)s_ti[k] * HF + hf], a);
        out[(size_t)b * HF + hf] = a;
    }
}

// ---------------- launch ----------------
extern "C" void kernel_launch(void* const* d_in, const int* in_sizes, int n_in,
                              void* d_out, int out_size) {
    const float* query  = (const float*)d_in[0];
    const float* keys   = (const float*)d_in[1];
    const float* values = (const float*)d_in[2];
    const void*  ts     = d_in[3];
    const void*  gs     = d_in[4];
    float* out = (float*)d_out;
    (void)in_sizes; (void)n_in; (void)out_size;

    cudaFuncSetAttribute(k_screen_pre, cudaFuncAttributeMaxDynamicSharedMemorySize, SMEM_SCREEN);
    cudaFuncSetAttribute(k_screen_main, cudaFuncAttributeMaxDynamicSharedMemorySize, SMEM_SCREEN);
    cudaFuncSetAttribute(k_finish, cudaFuncAttributeMaxDynamicSharedMemorySize, CAP * 8);

    k_setup<<<SB_END, 256>>>(query, keys, ts, gs);             // init+decay+qnorm+prep[316,391)
    k_screen_pre<<<dim3(8, 8), 256, SMEM_SCREEN>>>();          // K-split prepass -> 2 planes
    k_t16<<<NB, 256>>>();                                      // bounds (+per-qt) + emit
    k_mid<<<1 + PREP_U0 * 4, 256>>>(keys);                     // worklists + fix-up prep
    k_screen_main<<<dim3(8, PRE_C0 * 2), 256, SMEM_SCREEN>>>();// worklist-driven screen + emit
    k_finish<<<NB, 256, CAP * 8>>>(keys, values, out);         // rescore+select+softmax+gather
}

// round 16
// speedup vs baseline: 2.6732x; 1.0185x over previous
#include <cuda_runtime.h>
#include <math.h>
#include <stdint.h>

#define NB      1024
#define NN      100000
#define DD      512
#define HF      672
#define TOPK    16
#define CHUNK   256
#define NCHUNK  391            // ceil(NN/256); 391*256 = 100096
#define PRE_C0  389            // prepass chunks 389,390
#define PRE_N0  (PRE_C0*CHUNK) // 99584
#define PREP_U0 316            // chunks >= this prepped unconditionally in setup
#define CAP     4096
#define EPSM    1e-3f          // bf16 screening margin (~14 sigma)
#define DECAYF  0.995f
#define TEMP    0.1f
#define NEGINF  (-1e30f)

#define ROWB    80             // padded smem row stride (bytes) for 32 bf16
#define STAGEB  (2 * 128 * ROWB)   // 20480 B per stage
#define SMEM_SCREEN (4 * STAGEB)   // 81920 B, 4-stage ring
#define NPERS   296            // persistent blocks: 2/SM x 148

// setup block partition
#define SB_QN   391
#define SB_PP   (SB_QN + 128)              // 519
#define SB_PU   (SB_PP + 8)                // 527
#define SB_END  (SB_PU + (PRE_C0 - PREP_U0) * 4)   // 819

// ---------------- device scratch ----------------
__device__ float    g_decay[NN];
__device__ float    g_scale[NCHUNK * CHUNK];
__device__ float    g_qn[(size_t)NB * DD];
__device__ __align__(16) char g_qbf[(size_t)NB * DD * 2];
__device__ __align__(16) char g_kbf[(size_t)NCHUNK * CHUNK * DD * 2];
__device__ float    g_presims[(size_t)2 * NB * 512];   // two K-half partial planes
__device__ float    g_temit[NB];
__device__ int      g_ccnt[NB];
__device__ int      g_ci[(size_t)NB * CAP];
__device__ unsigned g_tmin_enc;
__device__ int      g_wl[PRE_C0];
__device__ int      g_wlcnt;
__device__ int      g_ticket;

// ---------------- helpers ----------------
__device__ __forceinline__ unsigned fenc(float f) {
    unsigned u = __float_as_uint(f);
    return (u & 0x80000000u) ? ~u : (u | 0x80000000u);
}
__device__ __forceinline__ float fdec(unsigned u) {
    u = (u & 0x80000000u) ? (u ^ 0x80000000u) : ~u;
    return __uint_as_float(u);
}
__device__ __forceinline__ unsigned long long packvi(float v, int ix) {
    return ((unsigned long long)fenc(v) << 32) | (unsigned)(0xFFFFFFFFu - (unsigned)ix);
}
__device__ __forceinline__ float pack_v(unsigned long long p) { return fdec((unsigned)(p >> 32)); }
__device__ __forceinline__ int   pack_i(unsigned long long p) { return (int)(0xFFFFFFFFu - (unsigned)p); }

__device__ __forceinline__ uint32_t packbf(float a, float b) {
    uint32_t r;
    asm("cvt.rn.bf16x2.f32 %0, %1, %2;" : "=r"(r) : "f"(b), "f"(a));
    return r;
}
__device__ __forceinline__ uint32_t smem_u32(const void* p) {
    uint32_t a;
    asm("{ .reg .u64 t; cvta.to.shared.u64 t, %1; cvt.u32.u64 %0, t; }" : "=r"(a) : "l"(p));
    return a;
}
__device__ __forceinline__ void cp16s(uint32_t dst, const void* src) {
    asm volatile("cp.async.cg.shared.global [%0], [%1], 16;" :: "r"(dst), "l"(src));
}
#define CP_COMMIT() asm volatile("cp.async.commit_group;")
#define CP_WAIT(n)  asm volatile("cp.async.wait_group %0;" :: "n"(n))

__device__ __forceinline__ void ldsm_x4(uint32_t& r0, uint32_t& r1, uint32_t& r2,
                                        uint32_t& r3, uint32_t addr) {
    asm volatile("ldmatrix.sync.aligned.m8n8.x4.shared.b16 {%0,%1,%2,%3}, [%4];"
                 : "=r"(r0), "=r"(r1), "=r"(r2), "=r"(r3) : "r"(addr));
}
__device__ __forceinline__ void mma16816(float* c, const uint32_t* a, const uint32_t* b) {
    asm volatile("mma.sync.aligned.m16n8k16.row.col.f32.bf16.bf16.f32 "
        "{%0,%1,%2,%3}, {%4,%5,%6,%7}, {%8,%9}, {%0,%1,%2,%3};"
        : "+f"(c[0]), "+f"(c[1]), "+f"(c[2]), "+f"(c[3])
        : "r"(a[0]), "r"(a[1]), "r"(a[2]), "r"(a[3]), "r"(b[0]), "r"(b[1]));
}
__device__ __forceinline__ float decay_of(const void* ts_raw, const void* gs_raw, int n) {
    const int* w = (const int*)ts_raw;
    bool is64 = (w[NN - 1] == 0);
    long long ts = is64 ? ((const long long*)ts_raw)[n] : (long long)w[n];
    int gs = ((const int*)gs_raw)[0];
    return powf(DECAYF, (float)(gs - (int)ts));
}
__device__ __forceinline__ bool chunk_active(int c) {
    float t = fdec(g_tmin_enc) - 2.0f * EPSM - 1e-4f;
    float dmax = g_decay[(c + 1) * CHUNK - 1];
    return dmax * 1.001f >= t;
}

// shared prep body: one (chunk, quarter) -> 64 rows of bf16*scale + g_scale
__device__ __forceinline__ void prep_quarter(const float* __restrict__ keys, int c, int quarter,
                                             bool local_decay, const void* ts, const void* gs) {
    int wid = threadIdx.x >> 5, lane = threadIdx.x & 31;
#pragma unroll
    for (int it = 0; it < 8; it++) {
        int r = quarter * 64 + wid * 8 + it;
        int n = c * CHUNK + r;
        bool ok = n < NN;
        float v[16]; float ss = 0.f;
        if (ok) {
            const float* kr = keys + (size_t)n * DD + lane * 16;
#pragma unroll
            for (int t = 0; t < 4; t++) {
                float4 x = *(const float4*)(kr + t * 4);
                v[t*4+0] = x.x; v[t*4+1] = x.y; v[t*4+2] = x.z; v[t*4+3] = x.w;
                ss = fmaf(x.x, x.x, fmaf(x.y, x.y, fmaf(x.z, x.z, fmaf(x.w, x.w, ss))));
            }
        } else {
#pragma unroll
            for (int j = 0; j < 16; j++) v[j] = 0.f;
        }
#pragma unroll
        for (int o = 16; o; o >>= 1) ss += __shfl_xor_sync(0xffffffffu, ss, o);
        float dk = ok ? (local_decay ? decay_of(ts, gs, n) : g_decay[n]) : 0.f;
        float sc = ok ? dk / fmaxf(sqrtf(ss), 1e-12f) : 0.f;
        if (lane == 0) g_scale[n] = sc;
        uint32_t h[8];
#pragma unroll
        for (int i = 0; i < 8; i++) h[i] = packbf(v[2*i] * sc, v[2*i+1] * sc);
        char* dst = g_kbf + (size_t)n * 1024 + lane * 32;
        *(uint4*)dst        = make_uint4(h[0], h[1], h[2], h[3]);
        *(uint4*)(dst + 16) = make_uint4(h[4], h[5], h[6], h[7]);
    }
}

// ---------------- fused setup ----------------
// [0,391): decay+init. [391,519): qnorm. [519,527): prepass prep. [527,819): prep [316,389).
__global__ void k_setup(const float* __restrict__ q, const float* __restrict__ keys,
                        const void* __restrict__ ts, const void* __restrict__ gs) {
    int bx = blockIdx.x;
    int tid = threadIdx.x;
    if (bx < SB_QN) {
        int n = bx * 256 + tid;
        if (n < NB) g_ccnt[n] = 0;
        if (n == 0) { g_tmin_enc = 0xFFFFFFFFu; g_ticket = 0; }
        if (n < NN) g_decay[n] = decay_of(ts, gs, n);
        return;
    }
    int wid = tid >> 5, lane = tid & 31;
    if (bx < SB_PP) {
        int b = (bx - SB_QN) * 8 + wid;
        const float* row = q + (size_t)b * DD + lane * 16;
        float v[16]; float ss = 0.f;
#pragma unroll
        for (int t = 0; t < 4; t++) {
            float4 x = *(const float4*)(row + t * 4);
            v[t*4+0] = x.x; v[t*4+1] = x.y; v[t*4+2] = x.z; v[t*4+3] = x.w;
            ss = fmaf(x.x, x.x, fmaf(x.y, x.y, fmaf(x.z, x.z, fmaf(x.w, x.w, ss))));
        }
#pragma unroll
        for (int o = 16; o; o >>= 1) ss += __shfl_xor_sync(0xffffffffu, ss, o);
        float inv = 1.0f / fmaxf(sqrtf(ss), 1e-12f);
#pragma unroll
        for (int j = 0; j < 16; j++) v[j] *= inv;
#pragma unroll
        for (int t = 0; t < 4; t++)
            *(float4*)(g_qn + (size_t)b * DD + lane * 16 + t * 4) =
                make_float4(v[t*4+0], v[t*4+1], v[t*4+2], v[t*4+3]);
        uint32_t h[8];
#pragma unroll
        for (int i = 0; i < 8; i++) h[i] = packbf(v[2*i], v[2*i+1]);
        char* dst = g_qbf + (size_t)b * 1024 + lane * 32;
        *(uint4*)dst        = make_uint4(h[0], h[1], h[2], h[3]);
        *(uint4*)(dst + 16) = make_uint4(h[4], h[5], h[6], h[7]);
        return;
    }
    if (bx < SB_PU) {
        int idx = bx - SB_PP;
        prep_quarter(keys, PRE_C0 + (idx >> 2), idx & 3, true, ts, gs);
        return;
    }
    int idx = bx - SB_PU;
    prep_quarter(keys, PREP_U0 + (idx >> 2), idx & 3, true, ts, gs);
}

// ---------------- HMMA screen body (shared by pre/main) ----------------
__device__ __forceinline__ void screen_tile(uint32_t sb, const char* qsrc, const char* ksrc,
                                            int slab0, int nslab, float acc[2][8][4]) {
    int tid = threadIdx.x;
    int wid = tid >> 5, lane = tid & 31;
    int warp_q = wid & 3, warp_n = wid >> 2;
    int r0i = (tid * 2) >> 2, u0 = (tid * 2) & 3;
    int r1i = (tid * 2 + 1) >> 2, u1 = (tid * 2 + 1) & 3;

#define LOAD_SLAB(s, st) do {                                                        \
    uint32_t qb_ = sb + (st) * STAGEB;                                               \
    uint32_t kb_ = qb_ + 128 * ROWB;                                                 \
    int as_ = slab0 + (s);                                                           \
    cp16s(qb_ + r0i * ROWB + u0 * 16, qsrc + (size_t)r0i * 1024 + as_ * 64 + u0 * 16); \
    cp16s(qb_ + r1i * ROWB + u1 * 16, qsrc + (size_t)r1i * 1024 + as_ * 64 + u1 * 16); \
    cp16s(kb_ + r0i * ROWB + u0 * 16, ksrc + (size_t)r0i * 1024 + as_ * 64 + u0 * 16); \
    cp16s(kb_ + r1i * ROWB + u1 * 16, ksrc + (size_t)r1i * 1024 + as_ * 64 + u1 * 16); \
} while (0)

    LOAD_SLAB(0, 0); CP_COMMIT();
    LOAD_SLAB(1, 1); CP_COMMIT();
    LOAD_SLAB(2, 2); CP_COMMIT();

    for (int s = 0; s < nslab; s++) {
        if (s <= nslab - 3)      CP_WAIT(2);
        else if (s == nslab - 2) CP_WAIT(1);
        else                     CP_WAIT(0);
        __syncthreads();
        if (s + 3 < nslab) { LOAD_SLAB(s + 3, (s + 3) & 3); CP_COMMIT(); }

        uint32_t qb = sb + (s & 3) * STAGEB;
        uint32_t kb = qb + 128 * ROWB;
#pragma unroll
        for (int ks = 0; ks < 2; ks++) {
            uint32_t a[2][4];
#pragma unroll
            for (int mt = 0; mt < 2; mt++) {
                int row = warp_q * 32 + mt * 16 + (lane & 15);
                int unit = ks * 2 + (lane >> 4);
                ldsm_x4(a[mt][0], a[mt][1], a[mt][2], a[mt][3],
                        qb + row * ROWB + unit * 16);
            }
            uint32_t bf[8][2];
#pragma unroll
            for (int jj = 0; jj < 4; jj++) {
                int nrow = warp_n * 64 + jj * 16 + (lane & 7) + ((lane >> 4) << 3);
                int unit = ks * 2 + ((lane >> 3) & 1);
                uint32_t b0, b1, b2, b3;
                ldsm_x4(b0, b1, b2, b3, kb + nrow * ROWB + unit * 16);
                bf[2*jj][0] = b0; bf[2*jj][1] = b1;
                bf[2*jj+1][0] = b2; bf[2*jj+1][1] = b3;
            }
#pragma unroll
            for (int mt = 0; mt < 2; mt++)
#pragma unroll
                for (int nt = 0; nt < 8; nt++)
                    mma16816(acc[mt][nt], a[mt], bf[nt]);
        }
    }
#undef LOAD_SLAB
}

// ---------------- prepass screen: grid (8, 8) = (qt, nq 0..3 x khalf 0..1) ----------------
__global__ void __launch_bounds__(256, 2) k_screen_pre() {
    int qt = blockIdx.x;
    int nq = blockIdx.y & 3, kh = blockIdx.y >> 2;
    int c = PRE_C0 + (nq >> 1), half = nq & 1;
    int n0 = c * CHUNK + half * 128;

    extern __shared__ __align__(16) char smb[];
    uint32_t sb = smem_u32(smb);
    int tid = threadIdx.x;
    int wid = tid >> 5, lane = tid & 31;
    int warp_q = wid & 3, warp_n = wid >> 2;

    float acc[2][8][4];
#pragma unroll
    for (int mt = 0; mt < 2; mt++)
#pragma unroll
        for (int nt = 0; nt < 8; nt++)
#pragma unroll
            for (int i = 0; i < 4; i++) acc[mt][nt][i] = 0.f;

    screen_tile(sb, g_qbf + (size_t)(qt * 128) * 1024, g_kbf + (size_t)n0 * 1024,
                kh * 8, 8, acc);

    float* plane = g_presims + (size_t)kh * NB * 512;
    int colbase = nq * 128;
#pragma unroll
    for (int mt = 0; mt < 2; mt++) {
        int q = qt * 128 + warp_q * 32 + mt * 16 + (lane >> 2);
#pragma unroll
        for (int nt = 0; nt < 8; nt++) {
            int loc = warp_n * 64 + nt * 8 + (lane & 3) * 2;
            *(float2*)&plane[(size_t)q * 512 + colbase + loc] =
                make_float2(acc[mt][nt][0], acc[mt][nt][1]);
            *(float2*)&plane[(size_t)(q + 8) * 512 + colbase + loc] =
                make_float2(acc[mt][nt][2], acc[mt][nt][3]);
        }
    }
}

// ---------------- t16: sum K-halves, 16x packed max-extraction, threshold + emit ----------------
__global__ void k_t16() {
    __shared__ float sv[512];
    __shared__ float svO[512];
    __shared__ unsigned long long s_best;
    int b = blockIdx.x, tid = threadIdx.x;
    int lane = tid & 31;
    const float* P0 = g_presims + (size_t)b * 512;
    const float* P1 = g_presims + (size_t)(NB + b) * 512;
#pragma unroll
    for (int s = tid; s < 512; s += 256) {
        float v = (PRE_N0 + s < NN) ? P0[s] + P1[s] : NEGINF;
        sv[s] = v; svO[s] = v;
    }
    float t = NEGINF;
    for (int r = 0; r < TOPK; r++) {
        if (tid == 0) s_best = 0ULL;
        __syncthreads();
        unsigned long long m = packvi(sv[tid], tid);
        unsigned long long m2 = packvi(sv[tid + 256], tid + 256);
        if (m2 > m) m = m2;
#pragma unroll
        for (int o = 16; o; o >>= 1) {
            unsigned long long om = __shfl_xor_sync(0xffffffffu, m, o);
            if (om > m) m = om;
        }
        if (lane == 0) atomicMax(&s_best, m);
        __syncthreads();
        unsigned long long w = s_best;
        int wi = pack_i(w);
        if (wi == tid) sv[tid] = NEGINF;
        if (wi == tid + 256) sv[tid + 256] = NEGINF;
        if (r == TOPK - 1) t = pack_v(w);
        __syncthreads();
    }
    float te = t - 2.0f * EPSM;
    if (tid == 0) {
        g_temit[b] = te;
        atomicMin(&g_tmin_enc, fenc(t));
    }
    for (int s = tid; s < 512; s += 256) {
        float v = svO[s];
        int n = PRE_N0 + s;
        if (v >= te && n < NN) {
            int pos = atomicAdd(&g_ccnt[b], 1);
            if (pos < CAP) g_ci[(size_t)b * CAP + pos] = n;
        }
    }
}

// ---------------- mid: block 0 builds global worklist; blocks 1.. = fix-up prep c<316 ----------------
__global__ void k_mid(const float* __restrict__ keys) {
    int wid = threadIdx.x >> 5, lane = threadIdx.x & 31;
    if (blockIdx.x == 0) {
        if (wid == 0) {
            float t = fdec(g_tmin_enc) - 2.0f * EPSM - 1e-4f;
            int cnt = 0;
            for (int base = 0; base < PRE_C0; base += 32) {
                int c = base + lane;
                bool act = (c < PRE_C0) && (g_decay[(c + 1) * CHUNK - 1] * 1.001f >= t);
                unsigned mask = __ballot_sync(0xffffffffu, act);
                if (act) g_wl[cnt + __popc(mask & ((1u << lane) - 1))] = c;
                cnt += __popc(mask);
            }
            if (lane == 0) g_wlcnt = cnt;
        }
        return;
    }
    int c = blockIdx.x - 1;                 // fix-up: chunks [0, PREP_U0)
    if (!chunk_active(c)) return;
    for (int qtr = 0; qtr < 4; qtr++) prep_quarter(keys, c, qtr, false, 0, 0);
}

// ---------------- persistent ticket-driven main screen ----------------
__global__ void __launch_bounds__(256, 2) k_screen_main() {
    extern __shared__ __align__(16) char smb[];
    uint32_t sb = smem_u32(smb);
    __shared__ int s_t;
    int tid = threadIdx.x;
    int wid = tid >> 5, lane = tid & 31;
    int warp_q = wid & 3, warp_n = wid >> 2;
    int total = g_wlcnt * 16;               // tiles: chunk-major, 16 per chunk (8 qt x 2 half)

    for (;;) {
        if (tid == 0) s_t = atomicAdd(&g_ticket, 1);
        __syncthreads();
        int t = s_t;
        if (t >= total) return;
        int c    = g_wl[t >> 4];
        int qt   = (t >> 1) & 7;
        int half = t & 1;
        int n0 = c * CHUNK + half * 128;

        float acc[2][8][4];
#pragma unroll
        for (int mt = 0; mt < 2; mt++)
#pragma unroll
            for (int nt = 0; nt < 8; nt++)
#pragma unroll
                for (int j = 0; j < 4; j++) acc[mt][nt][j] = 0.f;

        screen_tile(sb, g_qbf + (size_t)(qt * 128) * 1024, g_kbf + (size_t)n0 * 1024,
                    0, 16, acc);

        float tlo[2], thi[2];
#pragma unroll
        for (int mt = 0; mt < 2; mt++) {
            int q = qt * 128 + warp_q * 32 + mt * 16 + (lane >> 2);
            tlo[mt] = g_temit[q];
            thi[mt] = g_temit[q + 8];
        }
#pragma unroll
        for (int mt = 0; mt < 2; mt++) {
            int q = qt * 128 + warp_q * 32 + mt * 16 + (lane >> 2);
#pragma unroll
            for (int nt = 0; nt < 8; nt++) {
                int n = n0 + warp_n * 64 + nt * 8 + (lane & 3) * 2;
#pragma unroll
                for (int j = 0; j < 4; j++) {
                    float v = acc[mt][nt][j];
                    int qi = q + (j >> 1) * 8;
                    int ni = n + (j & 1);
                    float th = (j >> 1) ? thi[mt] : tlo[mt];
                    if (v >= th && ni < NN) {
                        int pos = atomicAdd(&g_ccnt[qi], 1);
                        if (pos < CAP) g_ci[(size_t)qi * CAP + pos] = ni;
                    }
                }
            }
        }
        __syncthreads();    // all compute done before next tile overwrites stages / s_t
    }
}

// ---------------- fused rescore + select + softmax + gather ----------------
__global__ void k_finish(const float* __restrict__ keys,
                         const float* __restrict__ values, float* __restrict__ out) {
    extern __shared__ float s_dyn[];
    float* s_cv = s_dyn;
    int*   s_ci = (int*)(s_dyn + CAP);
    __shared__ unsigned long long s_best;
    __shared__ float s_tv[16];
    __shared__ int   s_ti[16];
    __shared__ float s_w[16];

    int b = blockIdx.x, tid = threadIdx.x;
    int wid = tid >> 5, lane = tid & 31;
    int cnt = g_ccnt[b]; if (cnt > CAP) cnt = CAP;

    float qv[16];
#pragma unroll
    for (int t = 0; t < 4; t++) {
        float4 x = *(const float4*)(g_qn + (size_t)b * DD + lane * 16 + t * 4);
        qv[t*4+0] = x.x; qv[t*4+1] = x.y; qv[t*4+2] = x.z; qv[t*4+3] = x.w;
    }
    for (int i = wid; i < cnt; i += 8) {
        int n = g_ci[(size_t)b * CAP + i];
        const float* kr = keys + (size_t)n * DD + lane * 16;
        float s = 0.f;
#pragma unroll
        for (int t = 0; t < 4; t++) {
            float4 x = *(const float4*)(kr + t * 4);
            s = fmaf(qv[t*4+0], x.x, fmaf(qv[t*4+1], x.y,
                fmaf(qv[t*4+2], x.z, fmaf(qv[t*4+3], x.w, s))));
        }
#pragma unroll
        for (int o = 16; o; o >>= 1) s += __shfl_xor_sync(0xffffffffu, s, o);
        if (lane == 0) { s_cv[i] = s * g_scale[n]; s_ci[i] = n; }
    }
    __syncthreads();

    for (int r = 0; r < TOPK; r++) {
        if (tid == 0) s_best = 0ULL;
        __syncthreads();
        unsigned long long m = 0ULL;
        for (int i = tid; i < cnt; i += 256) {
            unsigned long long p = packvi(s_cv[i], s_ci[i]);
            if (p > m) m = p;
        }
#pragma unroll
        for (int o = 16; o; o >>= 1) {
            unsigned long long om = __shfl_xor_sync(0xffffffffu, m, o);
            if (om > m) m = om;
        }
        if (lane == 0 && m) atomicMax(&s_best, m);
        __syncthreads();
        unsigned long long w = s_best;
        int wi = pack_i(w);
        if (tid == 0) { s_tv[r] = pack_v(w); s_ti[r] = wi; }
        for (int i = tid; i < cnt; i += 256)
            if (s_ci[i] == wi) s_cv[i] = NEGINF;
        __syncthreads();
    }

    if (tid == 0) {
        float m = s_tv[0];
        float e[16], S = 0.f;
        for (int k = 0; k < 16; k++) { e[k] = expf((s_tv[k] - m) / TEMP); S += e[k]; }
        float spm = 0.f;
        for (int k = 0; k < 16; k++) {
            float p = e[k] / S;
            p = (s_tv[k] >= 0.0f) ? p : 0.f;
            s_w[k] = p; spm += p;
        }
        float inv = 1.0f / (spm + 1e-8f);
        for (int k = 0; k < 16; k++) s_w[k] *= inv;
    }
    __syncthreads();

    for (int hf = tid; hf < HF; hf += 256) {
        float a = 0.f;
#pragma unroll
        for (int k = 0; k < 16; k++)
            a = fmaf(s_w[k], values[(size_t)s_ti[k] * HF + hf], a);
        out[(size_t)b * HF + hf] = a;
    }
}

// ---------------- launch ----------------
extern "C" void kernel_launch(void* const* d_in, const int* in_sizes, int n_in,
                              void* d_out, int out_size) {
    const float* query  = (const float*)d_in[0];
    const float* keys   = (const float*)d_in[1];
    const float* values = (const float*)d_in[2];
    const void*  ts     = d_in[3];
    const void*  gs     = d_in[4];
    float* out = (float*)d_out;
    (void)in_sizes; (void)n_in; (void)out_size;

    cudaFuncSetAttribute(k_screen_pre, cudaFuncAttributeMaxDynamicSharedMemorySize, SMEM_SCREEN);
    cudaFuncSetAttribute(k_screen_main, cudaFuncAttributeMaxDynamicSharedMemorySize, SMEM_SCREEN);
    cudaFuncSetAttribute(k_finish, cudaFuncAttributeMaxDynamicSharedMemorySize, CAP * 8);

    k_setup<<<SB_END, 256>>>(query, keys, ts, gs);          // init+decay+qnorm+prep[316,391)
    k_screen_pre<<<dim3(8, 8), 256, SMEM_SCREEN>>>();       // K-split prepass -> 2 planes
    k_t16<<<NB, 256>>>();                                   // bounds + prepass candidates
    k_mid<<<1 + PREP_U0, 256>>>(keys);                      // worklist + fix-up prep
    k_screen_main<<<NPERS, 256, SMEM_SCREEN>>>();           // persistent ticket screen + emit
    k_finish<<<NB, 256, CAP * 8>>>(keys, values, out);      // rescore+select+softmax+gather
}